// round 10
// baseline (speedup 1.0000x reference)
#include <cuda_runtime.h>
#include <cstdint>

#define BB 1024
#define LL 512
#define TT 50
#define TSTART 48
#define TSTOP 49
#define LOG2E 1.4426950408889634f
#define LN2F  0.6931471805599453f

typedef unsigned long long ull;
typedef long long ll;

__device__ int g_perm[BB];

__device__ __forceinline__ float ex2f(float x){
    float r; asm("ex2.approx.ftz.f32 %0, %1;" : "=f"(r) : "f"(x)); return r;
}
__device__ __forceinline__ ull pack2(float x, float y){
    ull r; asm("mov.b64 %0, {%1,%2};" : "=l"(r) : "f"(x), "f"(y)); return r;
}
__device__ __forceinline__ void unpack2(ull v, float &x, float &y){
    asm("mov.b64 {%0,%1}, %2;" : "=f"(x), "=f"(y) : "l"(v));
}
__device__ __forceinline__ void ffma2(ull &d, ull a, ull b){
    asm("fma.rn.f32x2 %0, %1, %2, %0;" : "+l"(d) : "l"(a), "l"(b));
}
__device__ __forceinline__ ull add2(ull a, ull b){
    ull r; asm("add.rn.f32x2 %0, %1, %2;" : "=l"(r) : "l"(a), "l"(b)); return r;
}
__device__ __forceinline__ uint32_t redux_max_bits(float x){
    uint32_t r; asm("redux.sync.max.u32 %0, %1, 0xffffffff;" : "=r"(r) : "r"(__float_as_uint(x))); return r;
}
__device__ __forceinline__ uint32_t saddr(const void* p){
    return (uint32_t)__cvta_generic_to_shared(p);
}
__device__ __forceinline__ void cp8(uint32_t dst, const float* src){
    asm volatile("cp.async.ca.shared.global [%0], [%1], 8;" :: "r"(dst), "l"(src));
}
__device__ __forceinline__ void cp_commit(){ asm volatile("cp.async.commit_group;"); }
__device__ __forceinline__ void cp_wait5(){ asm volatile("cp.async.wait_group 5;"); }
__device__ __forceinline__ void cp_wait6(){ asm volatile("cp.async.wait_group 6;"); }

// single 50x50 mat-vec (epilogue use)
__device__ __forceinline__ void matvec50(const float* wb, const ull* E0, const ull* E1,
                                         float &s0, float &s1){
    const ulonglong2* vb2 = (const ulonglong2*)wb;
    ull A0[4] = {0,0,0,0}, A1[4] = {0,0,0,0};
#pragma unroll
    for (int q = 0; q < 13; q++){
        ulonglong2 z = vb2[q];
        ffma2(A0[(2*q)&3], E0[2*q], z.x);   ffma2(A1[(2*q)&3], E1[2*q], z.x);
        ffma2(A0[(2*q+1)&3], E0[2*q+1], z.y); ffma2(A1[(2*q+1)&3], E1[2*q+1], z.y);
    }
    ull t0 = add2(add2(A0[0],A0[1]), add2(A0[2],A0[3]));
    ull t1 = add2(add2(A1[0],A1[1]), add2(A1[2],A1[3]));
    float x, y;
    unpack2(t0,x,y); s0 = x + y;
    unpack2(t1,x,y); s1 = x + y;
}

// dual interleaved mat-vec: 2 chains sharing E, 104 packed FMAs from 26 LDS.128
__device__ __forceinline__ void matvec50x2(const float* w0, const float* w1,
                                           const ull* E0, const ull* E1,
                                           float &s00, float &s01, float &s10, float &s11){
    const ulonglong2* a = (const ulonglong2*)w0;
    const ulonglong2* c = (const ulonglong2*)w1;
    ull A[4]={0,0,0,0}, B[4]={0,0,0,0}, C[4]={0,0,0,0}, D[4]={0,0,0,0};
#pragma unroll
    for (int q = 0; q < 13; q++){
        ulonglong2 z0 = a[q], z1 = c[q];
        ffma2(A[(2*q)&3], E0[2*q], z0.x);   ffma2(B[(2*q)&3], E1[2*q], z0.x);
        ffma2(C[(2*q)&3], E0[2*q], z1.x);   ffma2(D[(2*q)&3], E1[2*q], z1.x);
        ffma2(A[(2*q+1)&3], E0[2*q+1], z0.y); ffma2(B[(2*q+1)&3], E1[2*q+1], z0.y);
        ffma2(C[(2*q+1)&3], E0[2*q+1], z1.y); ffma2(D[(2*q+1)&3], E1[2*q+1], z1.y);
    }
    float x, y;
    unpack2(add2(add2(A[0],A[1]),add2(A[2],A[3])), x, y); s00 = x + y;
    unpack2(add2(add2(B[0],B[1]),add2(B[2],B[3])), x, y); s01 = x + y;
    unpack2(add2(add2(C[0],C[1]),add2(C[2],C[3])), x, y); s10 = x + y;
    unpack2(add2(add2(D[0],D[1]),add2(D[2],D[3])), x, y); s11 = x + y;
}

// Longest-first schedule (counting sort by len desc) + output zeroing.
__global__ void __launch_bounds__(512) sched(const int* __restrict__ lens, float* __restrict__ out){
    __shared__ int hist[512];
    __shared__ int base[512];
    const int tid = threadIdx.x;
    if (tid == 0) out[0] = 0.f;
    hist[tid] = 0;
    __syncthreads();
    for (int i = tid; i < BB; i += 512)
        atomicAdd(&hist[LL - __ldg(&lens[i])], 1);
    __syncthreads();
    int cnt = hist[tid];
    for (int o = 1; o < 512; o <<= 1){
        int v = (tid >= o) ? hist[tid - o] : 0;
        __syncthreads();
        hist[tid] += v;
        __syncthreads();
    }
    base[tid] = hist[tid] - cnt;
    __syncthreads();
    for (int i = tid; i < BB; i += 512){
        int bin = LL - __ldg(&lens[i]);
        g_perm[atomicAdd(&base[bin], 1)] = i;
    }
}

__global__ void __launch_bounds__(128)
crf_fwd(const float* __restrict__ logits,
        const float* __restrict__ trans,
        const int*   __restrict__ labels,
        const int*   __restrict__ lens,
        float* __restrict__ out)
{
    __shared__ float ring[4][2][8][64];  // [warp][chain][slot][64]
    __shared__ float vbuf[4][2][2][64];  // [warp][chain][phase][64]
    __shared__ float xsh[2][2][64];      // [pair][chain][64] fwd final vectors
    __shared__ float offsh[2][2];

    const int warp  = threadIdx.x >> 5;
    const int lane  = threadIdx.x & 31;
    const int pairI = warp >> 1;
    const int dir   = warp & 1;                  // 0 fwd, 1 bwd
    const int base_ = blockIdx.x * 4 + pairI * 2;
    const int b0 = g_perm[base_], b1 = g_perm[base_ + 1];

    const int j0 = lane;
    const int j1 = lane + 32;
    const bool hasJ1 = (j1 < TT);

    const int len0 = __ldg(&lens[b0]), len1 = __ldg(&lens[b1]);
    const int h0 = len0 >> 1,          h1 = len1 >> 1;
    const int steps0 = dir ? (len0 - h0 - 1) : h0;
    const int steps1 = dir ? (len1 - h1 - 1) : h1;
    const int maxSteps = max(steps0, steps1);
    const int maxq0 = dir ? (len0 - 1 - h0) : max(h0 - 1, 0);
    const int maxq1 = dir ? (len1 - 1 - h1) : max(h1 - 1, 0);
    const float* __restrict__ rowp0 = logits + (ll)b0 * LL * TT;
    const float* __restrict__ rowp1 = logits + (ll)b1 * LL * TT;
    const int*   __restrict__ lab0  = labels + (ll)b0 * LL;
    const int*   __restrict__ lab1  = labels + (ll)b1 * LL;

    auto trow0 = [&](int q){ int m = min(q, maxq0); return dir ? (len0 - 1 - m) : m; };
    auto trow1 = [&](int q){ int m = min(q, maxq1); return dir ? (len1 - 1 - m) : m; };

    // ---- ring prologue: slots 0..6 for both chains, one group per slot
#pragma unroll
    for (int q = 0; q < 7; q++){
        if (lane < 25){
            cp8(saddr(&ring[warp][0][q][0]) + lane*8u, rowp0 + (ll)trow0(q)*TT + lane*2);
            cp8(saddr(&ring[warp][1][q][0]) + lane*8u, rowp1 + (ll)trow1(q)*TT + lane*2);
        }
        cp_commit();
    }

    // zero vbuf tails (slots >= 50 stay 0 forever)
    vbuf[warp][0][0][lane] = 0.f; vbuf[warp][0][0][lane+32] = 0.f;
    vbuf[warp][0][1][lane] = 0.f; vbuf[warp][0][1][lane+32] = 0.f;
    vbuf[warp][1][0][lane] = 0.f; vbuf[warp][1][0][lane+32] = 0.f;
    vbuf[warp][1][1][lane] = 0.f; vbuf[warp][1][1][lane+32] = 0.f;

    // E rows (fwd: E, bwd: E^T) — shared by both chains
    ull E0[26], E1[26];
#pragma unroll
    for (int p = 0; p < 25; p++){
        int k0 = 2*p, k1 = 2*p + 1;
        float e00, e01, e10 = 0.f, e11 = 0.f;
        if (!dir){
            e00 = __ldg(&trans[j0*TT + k0]); e01 = __ldg(&trans[j0*TT + k1]);
            if (hasJ1){ e10 = __ldg(&trans[j1*TT + k0]); e11 = __ldg(&trans[j1*TT + k1]); }
        } else {
            e00 = __ldg(&trans[k0*TT + j0]); e01 = __ldg(&trans[k1*TT + j0]);
            if (hasJ1){ e10 = __ldg(&trans[k0*TT + j1]); e11 = __ldg(&trans[k1*TT + j1]); }
        }
        E0[p] = pack2(ex2f(LOG2E*e00), ex2f(LOG2E*e01));
        E1[p] = hasJ1 ? pack2(ex2f(LOG2E*e10), ex2f(LOG2E*e11)) : 0ull;
    }
    E0[25] = 0ull; E1[25] = 0ull;

    // ---- score phase (both chains; overlaps prologue latency)
    float em = 0.f, tr = 0.f;
    {
        int ta = dir ? h0 : 0, tb = dir ? len0 : h0;
        for (int t = ta + lane; t < tb; t += 32){
            int lab = __ldg(&lab0[t]);
            int prv = (t == 0) ? TSTART : __ldg(&lab0[t - 1]);
            em += __ldg(&rowp0[(ll)t*TT + lab]);
            tr += __ldg(&trans[lab*TT + prv]);
        }
        ta = dir ? h1 : 0; tb = dir ? len1 : h1;
        for (int t = ta + lane; t < tb; t += 32){
            int lab = __ldg(&lab1[t]);
            int prv = (t == 0) ? TSTART : __ldg(&lab1[t - 1]);
            em += __ldg(&rowp1[(ll)t*TT + lab]);
            tr += __ldg(&trans[lab*TT + prv]);
        }
        if (dir && lane == 0){
            tr += __ldg(&trans[TSTOP*TT + __ldg(&lab0[len0 - 1])]);
            tr += __ldg(&trans[TSTOP*TT + __ldg(&lab1[len1 - 1])]);
        }
    }

    // ---- state init
    float m0lo, m0hi, m1lo, m1hi;
    int off0 = 0, off1 = 0;
    if (!dir){
        m0lo = 0.f; m0hi = (j1 == TSTART) ? 1.f : 0.f;
        m1lo = 0.f; m1hi = m0hi;
    } else {
        float u0 = ex2f(LOG2E * __ldg(&trans[TSTOP*TT + j0]));
        float u1 = hasJ1 ? ex2f(LOG2E * __ldg(&trans[TSTOP*TT + j1])) : 0.f;
        cp_wait6(); __syncwarp();               // slot 0 of both chains ready
        m0lo = u0 * ex2f(LOG2E * ring[warp][0][0][j0]);
        m0hi = hasJ1 ? (u1 * ex2f(LOG2E * ring[warp][0][0][j1])) : 0.f;
        m1lo = u0 * ex2f(LOG2E * ring[warp][1][0][j0]);
        m1hi = hasJ1 ? (u1 * ex2f(LOG2E * ring[warp][1][0][j1])) : 0.f;
    }
    // captured final states (init = state for steps==0)
    float f0lo = m0lo, f0hi = m0hi, f1lo = m1lo, f1hi = m1hi;
    int   foff0 = 0, foff1 = 0;

    int phase = 0;
    for (int i = 0; i < maxSteps; i++){
        float* w0 = &vbuf[warp][0][phase][0];
        float* w1 = &vbuf[warp][1][phase][0];
        w0[j0] = m0lo; w1[j0] = m1lo;
        if (hasJ1){ w0[j1] = m0hi; w1[j1] = m1hi; }

        cp_wait5();            // slots 0..i+1 landed
        __syncwarp();

        {   // prefetch slot i+7, both chains
            int qn = i + 7, s = qn & 7;
            if (lane < 25){
                cp8(saddr(&ring[warp][0][s][0]) + lane*8u, rowp0 + (ll)trow0(qn)*TT + lane*2);
                cp8(saddr(&ring[warp][1][s][0]) + lane*8u, rowp1 + (ll)trow1(qn)*TT + lane*2);
            }
            cp_commit();
        }

        const float* r0 = &ring[warp][0][(i + dir) & 7][0];
        const float* r1 = &ring[warp][1][(i + dir) & 7][0];
        float p00 = ex2f(LOG2E * r0[j0]);
        float p01 = hasJ1 ? ex2f(LOG2E * r0[j1]) : 0.f;
        float p10 = ex2f(LOG2E * r1[j0]);
        float p11 = hasJ1 ? ex2f(LOG2E * r1[j1]) : 0.f;

        float s00, s01, s10, s11;
        matvec50x2(w0, w1, E0, E1, s00, s01, s10, s11);

        m0lo = p00 * s00; m0hi = hasJ1 ? (p01 * s01) : 0.f;
        m1lo = p10 * s10; m1hi = hasJ1 ? (p11 * s11) : 0.f;

        if ((i & 3) == 3){     // renorm both chains
            uint32_t mb0 = redux_max_bits(fmaxf(m0lo, m0hi));
            uint32_t mb1 = redux_max_bits(fmaxf(m1lo, m1hi));
            int k0 = max((int)(mb0 >> 23) - 127, -126);
            int k1 = max((int)(mb1 >> 23) - 127, -126);
            off0 += k0; off1 += k1;
            m0lo *= __int_as_float((127 - k0) << 23);
            m0hi *= __int_as_float((127 - k0) << 23);
            m1lo *= __int_as_float((127 - k1) << 23);
            m1hi *= __int_as_float((127 - k1) << 23);
        }

        // capture each chain's state at its own end (uniform predicated copies)
        if (i + 1 == steps0){ f0lo = m0lo; f0hi = m0hi; foff0 = off0; }
        if (i + 1 == steps1){ f1lo = m1lo; f1hi = m1hi; foff1 = off1; }

        phase ^= 1;
    }

    if (dir){  // bwd epilogue: bare y = E^T z per chain
        float* w0 = &vbuf[warp][0][phase][0];
        float* w1 = &vbuf[warp][1][phase][0];
        w0[j0] = f0lo; w1[j0] = f1lo;
        if (hasJ1){ w0[j1] = f0hi; w1[j1] = f1hi; }
        __syncwarp();
        float s0, s1;
        matvec50(w0, E0, E1, s0, s1); f0lo = s0; f0hi = s1;
        matvec50(w1, E0, E1, s0, s1); f1lo = s0; f1hi = s1;
    } else {   // fwd publishes final vectors
        xsh[pairI][0][j0] = f0lo;  xsh[pairI][1][j0] = f1lo;
        if (hasJ1){ xsh[pairI][0][j1] = f0hi; xsh[pairI][1][j1] = f1hi; }
        if (lane == 0){ offsh[pairI][0] = (float)foff0; offsh[pairI][1] = (float)foff1; }
    }
    asm volatile("bar.sync %0, %1;" :: "r"(1 + pairI), "r"(64) : "memory");

    float sc = em + tr;
#pragma unroll
    for (int o = 16; o; o >>= 1) sc += __shfl_xor_sync(0xffffffffu, sc, o);

    if (!dir){
        if (lane == 0) atomicAdd(out, -sc * (1.0f / BB));
    } else {
        float d0 = f0lo * xsh[pairI][0][j0] + (hasJ1 ? f0hi * xsh[pairI][0][j1] : 0.f);
        float d1 = f1lo * xsh[pairI][1][j0] + (hasJ1 ? f1hi * xsh[pairI][1][j1] : 0.f);
#pragma unroll
        for (int o = 16; o; o >>= 1){
            d0 += __shfl_xor_sync(0xffffffffu, d0, o);
            d1 += __shfl_xor_sync(0xffffffffu, d1, o);
        }
        if (lane == 0){
            float part0 = LN2F * ((float)foff0 + offsh[pairI][0] + log2f(d0));
            float part1 = LN2F * ((float)foff1 + offsh[pairI][1] + log2f(d1));
            atomicAdd(out, (part0 + part1 - sc) * (1.0f / BB));
        }
    }
}

extern "C" void kernel_launch(void* const* d_in, const int* in_sizes, int n_in,
                              void* d_out, int out_size)
{
    const float* logits = (const float*)d_in[0];
    const float* trans  = (const float*)d_in[1];
    const int*   labels = (const int*)d_in[2];
    const int*   lens   = (const int*)d_in[3];
    float* out = (float*)d_out;
    sched<<<1, 512>>>(lens, out);
    crf_fwd<<<BB / 4, 128>>>(logits, trans, labels, lens, out);
}

// round 12
// speedup vs baseline: 1.4874x; 1.4874x over previous
#include <cuda_runtime.h>
#include <cstdint>

#define BB 1024
#define LL 512
#define TT 50
#define TSTART 48
#define TSTOP 49
#define LOG2E 1.4426950408889634f
#define LN2F  0.6931471805599453f

typedef unsigned long long ull;
typedef long long ll;

__device__ int g_perm[BB];

__device__ __forceinline__ float ex2f(float x){
    float r; asm("ex2.approx.ftz.f32 %0, %1;" : "=f"(r) : "f"(x)); return r;
}
__device__ __forceinline__ ull pack2(float x, float y){
    ull r; asm("mov.b64 %0, {%1,%2};" : "=l"(r) : "f"(x), "f"(y)); return r;
}
__device__ __forceinline__ void unpack2(ull v, float &x, float &y){
    asm("mov.b64 {%0,%1}, %2;" : "=f"(x), "=f"(y) : "l"(v));
}
__device__ __forceinline__ void ffma2(ull &d, ull a, ull b){
    asm("fma.rn.f32x2 %0, %1, %2, %0;" : "+l"(d) : "l"(a), "l"(b));
}
__device__ __forceinline__ ull add2(ull a, ull b){
    ull r; asm("add.rn.f32x2 %0, %1, %2;" : "=l"(r) : "l"(a), "l"(b)); return r;
}
__device__ __forceinline__ uint32_t redux_max_bits(float x){
    uint32_t r; asm("redux.sync.max.u32 %0, %1, 0xffffffff;" : "=r"(r) : "r"(__float_as_uint(x))); return r;
}
__device__ __forceinline__ uint32_t saddr(const void* p){
    return (uint32_t)__cvta_generic_to_shared(p);
}
__device__ __forceinline__ void cp8(uint32_t dst, const float* src){
    asm volatile("cp.async.ca.shared.global [%0], [%1], 8;" :: "r"(dst), "l"(src));
}
__device__ __forceinline__ void cp_commit(){ asm volatile("cp.async.commit_group;"); }
__device__ __forceinline__ void cp_wait5(){ asm volatile("cp.async.wait_group 5;"); }
__device__ __forceinline__ void cp_wait6(){ asm volatile("cp.async.wait_group 6;"); }

// 50x50 mat-vec: 52 packed FMAs from 13 LDS.128, 4 accumulator chains
__device__ __forceinline__ void matvec50(const float* wb, const ull* E0, const ull* E1,
                                         float &s0, float &s1){
    const ulonglong2* vb2 = (const ulonglong2*)wb;
    ull A0[4] = {0,0,0,0}, A1[4] = {0,0,0,0};
#pragma unroll
    for (int q = 0; q < 13; q++){
        ulonglong2 z = vb2[q];
        ffma2(A0[(2*q)&3], E0[2*q], z.x);     ffma2(A1[(2*q)&3], E1[2*q], z.x);
        ffma2(A0[(2*q+1)&3], E0[2*q+1], z.y); ffma2(A1[(2*q+1)&3], E1[2*q+1], z.y);
    }
    ull t0 = add2(add2(A0[0],A0[1]), add2(A0[2],A0[3]));
    ull t1 = add2(add2(A1[0],A1[1]), add2(A1[2],A1[3]));
    float x, y;
    unpack2(t0,x,y); s0 = x + y;
    unpack2(t1,x,y); s1 = x + y;
}

// Longest-first schedule (counting sort by len desc) + output zeroing.
__global__ void __launch_bounds__(512) sched(const int* __restrict__ lens, float* __restrict__ out){
    __shared__ int hist[512];
    __shared__ int base[512];
    const int tid = threadIdx.x;
    if (tid == 0) out[0] = 0.f;
    hist[tid] = 0;
    __syncthreads();
    for (int i = tid; i < BB; i += 512)
        atomicAdd(&hist[LL - __ldg(&lens[i])], 1);
    __syncthreads();
    int cnt = hist[tid];
    for (int o = 1; o < 512; o <<= 1){
        int v = (tid >= o) ? hist[tid - o] : 0;
        __syncthreads();
        hist[tid] += v;
        __syncthreads();
    }
    base[tid] = hist[tid] - cnt;
    __syncthreads();
    for (int i = tid; i < BB; i += 512){
        int bin = LL - __ldg(&lens[i]);
        g_perm[atomicAdd(&base[bin], 1)] = i;
    }
}

#define GRID 296
#define R2B  216   // blocks that take a second (folded short) pair

__global__ void __launch_bounds__(128)
crf_fwd(const float* __restrict__ logits,
        const float* __restrict__ trans,
        const int*   __restrict__ labels,
        const int*   __restrict__ lens,
        float* __restrict__ out)
{
    __shared__ float ring[4][8][64];   // per-warp 8-deep logits-row ring
    __shared__ float vbuf[4][2][64];   // per-warp double-buffered vector broadcast
    __shared__ float xsh[2][64];       // fwd warp's final vector, per pair
    __shared__ float offsh[2];

    const int warp  = threadIdx.x >> 5;
    const int lane  = threadIdx.x & 31;
    const int pairI = warp >> 1;
    const int dir   = warp & 1;                 // 0 fwd, 1 bwd
    const int bid   = blockIdx.x;

    const int j0 = lane;
    const int j1 = lane + 32;
    const bool hasJ1 = (j1 < TT);

    // vbuf tails (slots >= 50) must stay 0 forever
    vbuf[warp][0][lane] = 0.f; vbuf[warp][0][lane+32] = 0.f;
    vbuf[warp][1][lane] = 0.f; vbuf[warp][1][lane+32] = 0.f;

    // E rows (fwd: E, bwd: E^T) — constant across both pairs; load once
    ull E0[26], E1[26];
#pragma unroll
    for (int p = 0; p < 25; p++){
        int k0 = 2*p, k1 = 2*p + 1;
        float e00, e01, e10 = 0.f, e11 = 0.f;
        if (!dir){
            e00 = __ldg(&trans[j0*TT + k0]); e01 = __ldg(&trans[j0*TT + k1]);
            if (hasJ1){ e10 = __ldg(&trans[j1*TT + k0]); e11 = __ldg(&trans[j1*TT + k1]); }
        } else {
            e00 = __ldg(&trans[k0*TT + j0]); e01 = __ldg(&trans[k1*TT + j0]);
            if (hasJ1){ e10 = __ldg(&trans[k0*TT + j1]); e11 = __ldg(&trans[k1*TT + j1]); }
        }
        E0[p] = pack2(ex2f(LOG2E*e00), ex2f(LOG2E*e01));
        E1[p] = hasJ1 ? pack2(ex2f(LOG2E*e10), ex2f(LOG2E*e11)) : 0ull;
    }
    E0[25] = 0ull; E1[25] = 0ull;

    for (int r = 0; r < 2; r++){
        if (r == 1 && bid >= R2B) break;
        // round 1: pairs 0..591 (longest); round 2: folded pairs 592..1023 (shortest to earliest blocks)
        const int slotIdx = (r == 0) ? (bid * 2 + pairI)
                                     : (2*GRID + 2 * (R2B - 1 - bid) + pairI);
        const int b = g_perm[slotIdx];

        const int len = __ldg(&lens[b]);
        const int h   = len >> 1;
        const int steps = dir ? (len - h - 1) : h;
        const int maxq  = dir ? (len - 1 - h) : max(h - 1, 0);
        const float* __restrict__ rowp   = logits + (ll)b * LL * TT;
        const int*   __restrict__ labrow = labels + (ll)b * LL;

        auto trow = [&](int q){ int m = min(q, maxq); return dir ? (len - 1 - m) : m; };

        // ---- ring prologue: slots 0..6
#pragma unroll
        for (int q = 0; q < 7; q++){
            if (lane < 25)
                cp8(saddr(&ring[warp][q][0]) + lane*8u, rowp + (ll)trow(q)*TT + lane*2);
            cp_commit();
        }

        // ---- score phase (lane-parallel; overlaps prologue DRAM latency)
        float em = 0.f, tr = 0.f;
        {
            int ta = dir ? h : 0;
            int tb = dir ? len : h;
            for (int t = ta + lane; t < tb; t += 32){
                int lab = __ldg(&labrow[t]);
                int prv = (t == 0) ? TSTART : __ldg(&labrow[t - 1]);
                em += __ldg(&rowp[(ll)t*TT + lab]);
                tr += __ldg(&trans[lab*TT + prv]);
            }
            if (dir && lane == 0)
                tr += __ldg(&trans[TSTOP*TT + __ldg(&labrow[len - 1])]);
        }

        // ---- state init
        float mlo, mhi;
        int off = 0;
        if (!dir){
            mlo = 0.f; mhi = (j1 == TSTART) ? 1.f : 0.f;
        } else {
            float u0 = ex2f(LOG2E * __ldg(&trans[TSTOP*TT + j0]));
            float u1 = hasJ1 ? ex2f(LOG2E * __ldg(&trans[TSTOP*TT + j1])) : 0.f;
            cp_wait6(); __syncwarp();           // slot 0 (row len-1) ready (stale groups drain first)
            mlo = u0 * ex2f(LOG2E * ring[warp][0][j0]);
            mhi = hasJ1 ? (u1 * ex2f(LOG2E * ring[warp][0][j1])) : 0.f;
        }

#define STEP(I, PH) { \
        float* wb = &vbuf[warp][PH][0]; \
        wb[j0] = mlo; \
        if (hasJ1) wb[j1] = mhi; \
        cp_wait5(); \
        __syncwarp(); \
        { int qn = (I) + 7; \
          if (lane < 25) cp8(saddr(&ring[warp][qn & 7][0]) + lane*8u, rowp + (ll)trow(qn)*TT + lane*2); \
          cp_commit(); } \
        const float* srow = &ring[warp][((I) + dir) & 7][0]; \
        float p0 = ex2f(LOG2E * srow[j0]); \
        float p1 = hasJ1 ? ex2f(LOG2E * srow[j1]) : 0.f; \
        float s0, s1; \
        matvec50(wb, E0, E1, s0, s1); \
        mlo = p0 * s0; \
        mhi = hasJ1 ? (p1 * s1) : 0.f; }

#define RENORM { \
        uint32_t mb = redux_max_bits(fmaxf(mlo, mhi)); \
        int k = max((int)(mb >> 23) - 127, -126); \
        off += k; \
        float scn = __int_as_float((127 - k) << 23); \
        mlo *= scn; mhi *= scn; }

        int i = 0;
        for (; i + 4 <= steps; i += 4){
            STEP(i,   0); STEP(i+1, 1); STEP(i+2, 0); STEP(i+3, 1);
            RENORM;
        }
        for (; i < steps; i++){
            STEP(i, (i & 1));
            if ((i & 3) == 3) RENORM;
        }
#undef STEP
#undef RENORM

        if (dir){   // bwd epilogue: bare y = E^T z
            float* wb = &vbuf[warp][steps & 1][0];
            wb[j0] = mlo;
            if (hasJ1) wb[j1] = mhi;
            __syncwarp();
            float s0, s1;
            matvec50(wb, E0, E1, s0, s1);
            mlo = s0; mhi = s1;
        } else {    // fwd publishes final vector + offset
            xsh[pairI][j0] = mlo;
            if (hasJ1) xsh[pairI][j1] = mhi;
            if (lane == 0) offsh[pairI] = (float)off;
        }
        asm volatile("bar.sync %0, %1;" :: "r"(1 + pairI), "r"(64) : "memory");

        float sc = em + tr;
#pragma unroll
        for (int o = 16; o; o >>= 1) sc += __shfl_xor_sync(0xffffffffu, sc, o);

        if (!dir){
            if (lane == 0) atomicAdd(out, -sc * (1.0f / BB));
        } else {
            float d = mlo * xsh[pairI][j0] + (hasJ1 ? mhi * xsh[pairI][j1] : 0.f);
#pragma unroll
            for (int o = 16; o; o >>= 1) d += __shfl_xor_sync(0xffffffffu, d, o);
            if (lane == 0){
                float part = LN2F * ((float)off + offsh[pairI] + log2f(d));
                atomicAdd(out, (part - sc) * (1.0f / BB));
            }
        }
        // protect xsh/offsh reuse by the next pair
        asm volatile("bar.sync %0, %1;" :: "r"(1 + pairI), "r"(64) : "memory");
    }
}

extern "C" void kernel_launch(void* const* d_in, const int* in_sizes, int n_in,
                              void* d_out, int out_size)
{
    const float* logits = (const float*)d_in[0];
    const float* trans  = (const float*)d_in[1];
    const int*   labels = (const int*)d_in[2];
    const int*   lens   = (const int*)d_in[3];
    float* out = (float*)d_out;
    sched<<<1, 512>>>(lens, out);
    crf_fwd<<<GRID, 128>>>(logits, trans, labels, lens, out);
}